// round 5
// baseline (speedup 1.0000x reference)
#include <cuda_runtime.h>
#include <math.h>

// Split-KV (flash-decoding) stage-2 merge. B=256, H=32, S=16, D=128, fp32.
//
// out[b,h,d] = sum_s w[s] * att_out[b,h,s,d] / sum_s w[s]
//   w[s] = exp(lse[s] - max_valid lse), valid iff per_split*s < seq_len
//   per_split = ceil(ceil(seq_len/splits)/32)*32
//
// Key structural facts exploited:
//  * valid splits form a PREFIX: valid(s) <=> s < nv, nv = ceil(seq_len/per_split)
//  * so the accumulation loop has a known warp-uniform trip count and loads can
//    be front-batched (8 predicated LDG.E.128 in flight) instead of one per
//    branchy iteration -> MLP_eff ~8 instead of ~1.
//
// One warp per (b,h). Lane owns one float4 of D. 1024 blocks x 256 threads, exact.

#define B_DIM 256
#define H_DIM 32
#define S_DIM 16
#define D_DIM 128
#define MIN_BLOCK_KV 32
#define LOG2E 1.4426950408889634f

__global__ __launch_bounds__(256, 4)
void splitkv_merge_kernel(const float* __restrict__ att_out,
                          const float* __restrict__ att_lse,
                          const int*   __restrict__ kv_indptr,
                          const int*   __restrict__ num_kv_splits,
                          float*       __restrict__ out)
{
    const int warp_id = (blockIdx.x * blockDim.x + threadIdx.x) >> 5;  // (b,h) pair
    const int lane    = threadIdx.x & 31;
    const int b       = warp_id >> 5;            // H_DIM == 32

    // ---- per-batch split geometry (warp-uniform) ----
    const int seq_len = kv_indptr[b + 1] - kv_indptr[b];
    const int splits  = num_kv_splits[b];
    const int per_split = ((((seq_len + splits - 1) / splits) + MIN_BLOCK_KV - 1)
                           >> 5) << 5;
    // valid splits are exactly s in [0, nv)
    const int nv = (seq_len + per_split - 1) / per_split;   // 1..16

    // ---- LSE stats: lane s (< nv) holds split s ----
    float lse = -INFINITY;
    if (lane < nv)
        lse = att_lse[(long)warp_id * S_DIM + lane];

    float m = lse;
    #pragma unroll
    for (int o = 16; o > 0; o >>= 1)
        m = fmaxf(m, __shfl_xor_sync(0xffffffffu, m, o));

    float w = (lane < nv) ? exp2f((lse - m) * LOG2E) : 0.0f;

    float esum = w;
    #pragma unroll
    for (int o = 16; o > 0; o >>= 1)
        esum += __shfl_xor_sync(0xffffffffu, esum, o);
    const float inv_esum = 1.0f / esum;

    // ---- weighted accumulation: batches of 8 front-issued predicated loads ----
    const float4* __restrict__ src =
        reinterpret_cast<const float4*>(att_out) + (long)warp_id * (S_DIM * D_DIM / 4);

    float4 acc = make_float4(0.f, 0.f, 0.f, 0.f);

    #pragma unroll
    for (int s0 = 0; s0 < S_DIM; s0 += 8) {
        if (s0 < nv) {                       // warp-uniform batch skip
            float  ws[8];
            float4 v[8];
            #pragma unroll
            for (int j = 0; j < 8; ++j) {
                const int s = s0 + j;
                ws[j] = __shfl_sync(0xffffffffu, w, s);
                if (s < nv)                  // predicated LDG, front-batched
                    v[j] = src[s * (D_DIM / 4) + lane];
                else
                    v[j] = make_float4(0.f, 0.f, 0.f, 0.f);
            }
            #pragma unroll
            for (int j = 0; j < 8; ++j) {
                acc.x = fmaf(ws[j], v[j].x, acc.x);
                acc.y = fmaf(ws[j], v[j].y, acc.y);
                acc.z = fmaf(ws[j], v[j].z, acc.z);
                acc.w = fmaf(ws[j], v[j].w, acc.w);
            }
        }
    }

    acc.x *= inv_esum;
    acc.y *= inv_esum;
    acc.z *= inv_esum;
    acc.w *= inv_esum;

    reinterpret_cast<float4*>(out)[(long)warp_id * (D_DIM / 4) + lane] = acc;
}

extern "C" void kernel_launch(void* const* d_in, const int* in_sizes, int n_in,
                              void* d_out, int out_size)
{
    const float* att_out       = (const float*)d_in[0];
    const float* att_lse       = (const float*)d_in[1];
    // d_in[2] = q, d_in[3] = v_buffer : unused by the merge (shape-only in ref)
    const int*   kv_indptr     = (const int*)d_in[4];
    const int*   num_kv_splits = (const int*)d_in[5];
    float*       out           = (float*)d_out;

    // 8192 (b,h) warps, 8 warps per block -> exactly 1024 blocks, no tail
    splitkv_merge_kernel<<<(B_DIM * H_DIM) / 8, 256>>>(att_out, att_lse,
                                                       kv_indptr, num_kv_splits, out);
}

// round 6
// speedup vs baseline: 1.1577x; 1.1577x over previous
#include <cuda_runtime.h>
#include <math.h>

// Split-KV (flash-decoding) stage-2 merge. B=256, H=32, S=16, D=128, fp32.
//
// out[b,h,d] = sum_s w[s]*att_out[b,h,s,d] / sum_s w[s]
//   w[s] = exp(lse[s]-max), valid splits are a PREFIX: s < nv,
//   nv = ceil(seq_len/per_split), per_split = ceil(ceil(seq_len/splits)/32)*32.
//
// R5 design point (from R2 ncu: occ=38.5%, regs=61, DRAM=35%):
//   * 4-wide predicated load batches (MLP 4) instead of 8-wide -> ~40 regs
//   * 128-thread blocks, 2048 blocks -> finer scheduling, less wave tail
//   * 32-bit indexing only (67MB max byte offset fits)
// Target: ~70% occupancy * MLP 4 >> LSU/DRAM saturation point.

#define B_DIM 256
#define H_DIM 32
#define S_DIM 16
#define D_DIM 128
#define LOG2E 1.4426950408889634f

__global__ __launch_bounds__(128)
void splitkv_merge_kernel(const float* __restrict__ att_out,
                          const float* __restrict__ att_lse,
                          const int*   __restrict__ kv_indptr,
                          const int*   __restrict__ num_kv_splits,
                          float*       __restrict__ out)
{
    const unsigned warp_id = (blockIdx.x * 128u + threadIdx.x) >> 5;  // (b,h)
    const unsigned lane    = threadIdx.x & 31u;
    const unsigned b       = warp_id >> 5;               // H_DIM == 32

    // ---- per-batch split geometry (warp-uniform) ----
    const int seq_len = kv_indptr[b + 1] - kv_indptr[b];
    const int splits  = num_kv_splits[b];
    const int per_split = ((((seq_len + splits - 1) / splits) + 31) >> 5) << 5;
    const int nv = (seq_len + per_split - 1) / per_split;    // 1..16 valid prefix

    // ---- LSE stats: lane s (< nv) holds split s ----
    float lse = -INFINITY;
    if ((int)lane < nv)
        lse = att_lse[warp_id * S_DIM + lane];

    float m = lse;
    #pragma unroll
    for (int o = 16; o > 0; o >>= 1)
        m = fmaxf(m, __shfl_xor_sync(0xffffffffu, m, o));

    float w = ((int)lane < nv) ? exp2f((lse - m) * LOG2E) : 0.0f;

    float esum = w;
    #pragma unroll
    for (int o = 16; o > 0; o >>= 1)
        esum += __shfl_xor_sync(0xffffffffu, esum, o);
    const float inv_esum = 1.0f / esum;

    // ---- weighted accumulation: 4-wide predicated load batches ----
    // 32-bit indexing: max element index 8192*2048 = 16.7M < 2^31.
    const float4* __restrict__ src =
        reinterpret_cast<const float4*>(att_out) + warp_id * (S_DIM * D_DIM / 4u);

    float4 acc = make_float4(0.f, 0.f, 0.f, 0.f);

    #pragma unroll
    for (int s0 = 0; s0 < S_DIM; s0 += 4) {
        if (s0 < nv) {                          // warp-uniform batch skip
            float4 v0, v1, v2, v3;
            v0 = v1 = v2 = v3 = make_float4(0.f, 0.f, 0.f, 0.f);
            // front-batched predicated loads (4 LDG.E.128 in flight)
            if (s0 + 0 < nv) v0 = src[(s0 + 0) * (D_DIM / 4) + lane];
            if (s0 + 1 < nv) v1 = src[(s0 + 1) * (D_DIM / 4) + lane];
            if (s0 + 2 < nv) v2 = src[(s0 + 2) * (D_DIM / 4) + lane];
            if (s0 + 3 < nv) v3 = src[(s0 + 3) * (D_DIM / 4) + lane];

            float ws;
            ws = __shfl_sync(0xffffffffu, w, s0 + 0);
            acc.x = fmaf(ws, v0.x, acc.x); acc.y = fmaf(ws, v0.y, acc.y);
            acc.z = fmaf(ws, v0.z, acc.z); acc.w = fmaf(ws, v0.w, acc.w);
            ws = __shfl_sync(0xffffffffu, w, s0 + 1);
            acc.x = fmaf(ws, v1.x, acc.x); acc.y = fmaf(ws, v1.y, acc.y);
            acc.z = fmaf(ws, v1.z, acc.z); acc.w = fmaf(ws, v1.w, acc.w);
            ws = __shfl_sync(0xffffffffu, w, s0 + 2);
            acc.x = fmaf(ws, v2.x, acc.x); acc.y = fmaf(ws, v2.y, acc.y);
            acc.z = fmaf(ws, v2.z, acc.z); acc.w = fmaf(ws, v2.w, acc.w);
            ws = __shfl_sync(0xffffffffu, w, s0 + 3);
            acc.x = fmaf(ws, v3.x, acc.x); acc.y = fmaf(ws, v3.y, acc.y);
            acc.z = fmaf(ws, v3.z, acc.z); acc.w = fmaf(ws, v3.w, acc.w);
        }
    }

    acc.x *= inv_esum;
    acc.y *= inv_esum;
    acc.z *= inv_esum;
    acc.w *= inv_esum;

    reinterpret_cast<float4*>(out)[warp_id * (D_DIM / 4u) + lane] = acc;
}

extern "C" void kernel_launch(void* const* d_in, const int* in_sizes, int n_in,
                              void* d_out, int out_size)
{
    const float* att_out       = (const float*)d_in[0];
    const float* att_lse       = (const float*)d_in[1];
    // d_in[2] = q, d_in[3] = v_buffer : unused (shape-only in the reference)
    const int*   kv_indptr     = (const int*)d_in[4];
    const int*   num_kv_splits = (const int*)d_in[5];
    float*       out           = (float*)d_out;

    // 8192 (b,h) warps, 4 warps per 128-thread block -> 2048 blocks exact
    splitkv_merge_kernel<<<(B_DIM * H_DIM) / 4, 128>>>(att_out, att_lse,
                                                       kv_indptr, num_kv_splits, out);
}